// round 9
// baseline (speedup 1.0000x reference)
#include <cuda_runtime.h>
#include <cuda_fp16.h>
#include <cstdint>

// Problem constants
#define Bb 8
#define Tt 1024
#define Cc 1536
#define Hh 12
#define Dd 128
#define Ff 6144          // 4*C
#define BT 8192          // B*T
#define EPSF 1e-5f

// ---------------------------------------------------------------------------
// Scratch (static __device__ arrays; no runtime allocation)
// ---------------------------------------------------------------------------
__device__ __align__(256) __half g_h   [(size_t)BT * Cc];
__device__ __align__(256) __half g_qkv [(size_t)3 * BT * Cc];   // q | k | v
__device__ __align__(256) __half g_s   [(size_t)Bb * Hh * Tt * Tt];
__device__ __align__(256) __half g_o   [(size_t)BT * Cc];
__device__ __align__(256) __half g_f1  [(size_t)BT * Ff];
__device__ __align__(256) __half g_wqkvT[(size_t)3 * Hh * Dd * Cc];
__device__ __align__(256) __half g_woT [(size_t)Cc * Cc];
__device__ __align__(256) __half g_w1T [(size_t)Ff * Cc];
__device__ __align__(256) __half g_w2T [(size_t)Cc * Ff];
__device__ __align__(256) __half g_vt  [(size_t)Bb * Hh * Dd * Tt];
// fp32 residual-path tensors
__device__ float g_x1 [(size_t)BT * Cc];
__device__ float g_x2 [(size_t)BT * Cc];
__device__ float g_f2 [(size_t)BT * Cc];

// ---------------------------------------------------------------------------
// Baseline-PTX helpers (legal on plain compute_103)
// ---------------------------------------------------------------------------
__device__ __forceinline__ uint32_t smem_u32(const void* p) {
    uint32_t a;
    asm("{ .reg .u64 t; cvta.to.shared.u64 t, %1; cvt.u32.u64 %0, t; }" : "=r"(a) : "l"(p));
    return a;
}
__device__ __forceinline__ void cp16(uint32_t saddr, const void* gptr) {
    asm volatile("cp.async.cg.shared.global [%0], [%1], 16;" :: "r"(saddr), "l"(gptr));
}
#define CP_COMMIT() asm volatile("cp.async.commit_group;" ::: "memory")
#define CP_WAIT(n)  asm volatile("cp.async.wait_group %0;" :: "n"(n) : "memory")

__device__ __forceinline__ void ldsm4(uint32_t& r0, uint32_t& r1, uint32_t& r2,
                                      uint32_t& r3, uint32_t addr) {
    asm volatile("ldmatrix.sync.aligned.m8n8.x4.shared.b16 {%0,%1,%2,%3}, [%4];"
                 : "=r"(r0), "=r"(r1), "=r"(r2), "=r"(r3) : "r"(addr));
}
__device__ __forceinline__ void mma_f16(float* c, const uint32_t* a, const uint32_t* b) {
    asm volatile(
        "mma.sync.aligned.m16n8k16.row.col.f32.f16.f16.f32 "
        "{%0,%1,%2,%3}, {%4,%5,%6,%7}, {%8,%9}, {%0,%1,%2,%3};"
        : "+f"(c[0]), "+f"(c[1]), "+f"(c[2]), "+f"(c[3])
        : "r"(a[0]), "r"(a[1]), "r"(a[2]), "r"(a[3]), "r"(b[0]), "r"(b[1]));
}

// ---------------------------------------------------------------------------
// fp16 tensor-core NT GEMM: C[M,N] = alpha * A[M,K] * B[N,K]^T (+bias)(ReLU)(+add)
// Template CTAM:
//   128: CTA 128x128, 8 warps (4Mx2N, warp 32x64), 2 CTAs/SM
//   256: CTA 256x128, 8 warps (4Mx2N, warp 64x64), 1 CTA/SM
// K chunk 32, 4-stage cp.async. Smem rows: 32 halves padded to 80B stride.
// ---------------------------------------------------------------------------
template <int CTAM>
__global__ __launch_bounds__(256, (CTAM == 128) ? 2 : 1)
void hgemm(const __half* __restrict__ A, const __half* __restrict__ Bm,
           void* __restrict__ Cv, int M, int N, int K,
           int lda, int ldb, int ldc, float alpha,
           const float* __restrict__ bias, const float* __restrict__ addp,
           int doRelu, int outHalf, int causal, int kcap, int zdiv,
           long long aO, long long aI, long long bO, long long bI,
           long long cO, long long cI) {
    constexpr int WARP_M = CTAM / 4;          // 32 or 64
    constexpr int MSUB   = WARP_M / 16;       // 2 or 4
    constexpr uint32_t A_BYTES = CTAM * 80;   // per-stage A
    constexpr uint32_t STG = A_BYTES + 128 * 80;

    int m0 = blockIdx.y * CTAM, n0 = blockIdx.x * 128;
    if (causal && n0 > m0 + CTAM - 1) return;
    if (kcap && K > m0 + CTAM) K = m0 + CTAM;

    long long z = blockIdx.z;
    long long zo = z / zdiv, zi = z % zdiv;
    A  += zo * aO + zi * aI;
    Bm += zo * bO + zi * bI;
    size_t coff = (size_t)(zo * cO + zi * cI);
    const float* addb = addp ? addp + coff : nullptr;

    extern __shared__ __align__(16) char sm[];
    uint32_t sbase = smem_u32(sm);

    int tid = threadIdx.x, wid = tid >> 5, lane = tid & 31;
    int gid = lane >> 2, tig = lane & 3;
    int wm = (wid & 3) * WARP_M, wn = (wid >> 2) * 64;

    // cp.async mapping: 2 threads per row, 32B each
    int lrow = tid >> 1, lsel = tid & 1;
    const __half* aR = A + (size_t)(m0 + lrow) * lda + lsel * 16;
    const __half* bR = Bm + (size_t)(n0 + lrow) * ldb + lsel * 16;
    const __half* aR2 = aR + (size_t)128 * lda;   // used only for CTAM==256
    uint32_t dA = sbase + (uint32_t)(lrow * 80 + lsel * 32);
    uint32_t dB = sbase + A_BYTES + (uint32_t)(lrow * 80 + lsel * 32);

    int nch = K >> 5;
    auto issue = [&](int ch) {
        if (ch < nch) {
            uint32_t so = (uint32_t)(ch & 3) * STG;
            int k0 = ch * 32;
            cp16(dA + so,      aR + k0);
            cp16(dA + so + 16, aR + k0 + 8);
            if (CTAM == 256) {
                cp16(dA + so + 128u * 80u,      aR2 + k0);
                cp16(dA + so + 128u * 80u + 16, aR2 + k0 + 8);
            }
            cp16(dB + so,      bR + k0);
            cp16(dB + so + 16, bR + k0 + 8);
        }
        CP_COMMIT();
    };

    // ldmatrix lane offsets
    int g8 = lane >> 3, l8 = lane & 7;
    uint32_t aoff = (uint32_t)((((g8 & 1) * 8 + l8) * 80) + (g8 >> 1) * 16);
    uint32_t boff = A_BYTES + (uint32_t)((((g8 >> 1) * 8 + l8) * 80) + (g8 & 1) * 16);

    float acc[MSUB][8][4];
    #pragma unroll
    for (int i = 0; i < MSUB; i++)
        #pragma unroll
        for (int j = 0; j < 8; j++)
            #pragma unroll
            for (int r = 0; r < 4; r++) acc[i][j][r] = 0.f;

    issue(0); issue(1); issue(2);

    for (int ch = 0; ch < nch; ch++) {
        CP_WAIT(2);
        __syncthreads();
        issue(ch + 3);

        uint32_t stg = sbase + (uint32_t)(ch & 3) * STG;
        uint32_t aw = stg + aoff + (uint32_t)(wm * 80);
        uint32_t bw = stg + boff + (uint32_t)(wn * 80);

        #pragma unroll
        for (int s = 0; s < 2; s++) {
            uint32_t a[MSUB][4];
            #pragma unroll
            for (int i = 0; i < MSUB; i++)
                ldsm4(a[i][0], a[i][1], a[i][2], a[i][3],
                      aw + (uint32_t)(i * 16 * 80) + s * 32);
            uint32_t b[8][2];
            #pragma unroll
            for (int jj = 0; jj < 4; jj++) {
                uint32_t t0, t1, t2, t3;
                ldsm4(t0, t1, t2, t3, bw + (uint32_t)(jj * 16 * 80) + s * 32);
                b[2 * jj][0] = t0; b[2 * jj][1] = t1;
                b[2 * jj + 1][0] = t2; b[2 * jj + 1][1] = t3;
            }
            #pragma unroll
            for (int i = 0; i < MSUB; i++)
                #pragma unroll
                for (int j = 0; j < 8; j++)
                    mma_f16(acc[i][j], a[i], b[j]);
        }
    }

    // epilogue
    #pragma unroll
    for (int i = 0; i < MSUB; i++) {
        #pragma unroll
        for (int j = 0; j < 8; j++) {
            int r0 = m0 + wm + i * 16 + gid;
            int c  = n0 + wn + j * 8 + 2 * tig;
            #pragma unroll
            for (int hh = 0; hh < 2; hh++) {
                int r = r0 + hh * 8;
                float v0 = acc[i][j][2 * hh + 0] * alpha;
                float v1 = acc[i][j][2 * hh + 1] * alpha;
                if (bias) { v0 += bias[c]; v1 += bias[c + 1]; }
                if (doRelu) { v0 = fmaxf(v0, 0.f); v1 = fmaxf(v1, 0.f); }
                if (addb) {
                    const float* ap = addb + (size_t)r * ldc + c;
                    v0 += ap[0]; v1 += ap[1];
                }
                if (outHalf) {
                    __half2* cp = (__half2*)((__half*)Cv + coff + (size_t)r * ldc + c);
                    *cp = __floats2half2_rn(v0, v1);
                } else {
                    float2* cp = (float2*)((float*)Cv + coff + (size_t)r * ldc + c);
                    *cp = make_float2(v0, v1);
                }
            }
        }
    }
}

// ---------------------------------------------------------------------------
// Tiled transposes
// ---------------------------------------------------------------------------
__global__ void transpose_f2h(const float* __restrict__ in, __half* __restrict__ out,
                              int ldi, int ldo, int zdiv,
                              long long iO, long long iI, long long oO, long long oI) {
    __shared__ float tile[32][33];
    long long z = blockIdx.z;
    in  += (z / zdiv) * iO + (z % zdiv) * iI;
    out += (z / zdiv) * oO + (z % zdiv) * oI;
    int r0 = blockIdx.y * 32, c0 = blockIdx.x * 32;
    int tx = threadIdx.x & 31, ty = threadIdx.x >> 5;
    #pragma unroll
    for (int i = ty; i < 32; i += 8)
        tile[i][tx] = in[(size_t)(r0 + i) * ldi + c0 + tx];
    __syncthreads();
    #pragma unroll
    for (int i = ty; i < 32; i += 8)
        out[(size_t)(c0 + i) * ldo + r0 + tx] = __float2half_rn(tile[tx][i]);
}

__global__ void transpose_h2h(const __half* __restrict__ in, __half* __restrict__ out,
                              int ldi, int ldo, int zdiv,
                              long long iO, long long iI, long long oO, long long oI) {
    __shared__ __half tile[32][33];
    long long z = blockIdx.z;
    in  += (z / zdiv) * iO + (z % zdiv) * iI;
    out += (z / zdiv) * oO + (z % zdiv) * oI;
    int r0 = blockIdx.y * 32, c0 = blockIdx.x * 32;
    int tx = threadIdx.x & 31, ty = threadIdx.x >> 5;
    #pragma unroll
    for (int i = ty; i < 32; i += 8)
        tile[i][tx] = in[(size_t)(r0 + i) * ldi + c0 + tx];
    __syncthreads();
    #pragma unroll
    for (int i = ty; i < 32; i += 8)
        out[(size_t)(c0 + i) * ldo + r0 + tx] = tile[tx][i];
}

// ---------------------------------------------------------------------------
// Block reductions
// ---------------------------------------------------------------------------
__device__ __forceinline__ float blk_reduce_sum(float v) {
    __shared__ float sh[32];
    __syncthreads();
    int lane = threadIdx.x & 31, w = threadIdx.x >> 5;
    #pragma unroll
    for (int o = 16; o > 0; o >>= 1) v += __shfl_down_sync(0xffffffffu, v, o);
    if (lane == 0) sh[w] = v;
    __syncthreads();
    int nw = blockDim.x >> 5;
    if (w == 0) {
        v = (lane < nw) ? sh[lane] : 0.f;
        #pragma unroll
        for (int o = 16; o > 0; o >>= 1) v += __shfl_down_sync(0xffffffffu, v, o);
        if (lane == 0) sh[0] = v;
    }
    __syncthreads();
    return sh[0];
}
__device__ __forceinline__ float blk_reduce_max(float v) {
    __shared__ float sh[32];
    __syncthreads();
    int lane = threadIdx.x & 31, w = threadIdx.x >> 5;
    #pragma unroll
    for (int o = 16; o > 0; o >>= 1) v = fmaxf(v, __shfl_down_sync(0xffffffffu, v, o));
    if (lane == 0) sh[w] = v;
    __syncthreads();
    int nw = blockDim.x >> 5;
    if (w == 0) {
        v = (lane < nw) ? sh[lane] : -3.4e38f;
        #pragma unroll
        for (int o = 16; o > 0; o >>= 1) v = fmaxf(v, __shfl_down_sync(0xffffffffu, v, o));
        if (lane == 0) sh[0] = v;
    }
    __syncthreads();
    return sh[0];
}

// ---------------------------------------------------------------------------
// LayerNorm (fp32 stats, fp16 output)
// ---------------------------------------------------------------------------
__global__ void ln_kernel(const float* __restrict__ x, const float* __restrict__ g,
                          const float* __restrict__ b, __half* __restrict__ out) {
    size_t row = blockIdx.x;
    const float* xr = x + row * Cc;
    float s = 0.f, s2 = 0.f;
    for (int i = threadIdx.x; i < Cc; i += blockDim.x) {
        float v = xr[i]; s += v; s2 += v * v;
    }
    float S = blk_reduce_sum(s), S2 = blk_reduce_sum(s2);
    float mean = S * (1.0f / Cc);
    float var = S2 * (1.0f / Cc) - mean * mean;
    float inv = rsqrtf(var + EPSF);
    __half* orow = out + row * Cc;
    for (int i = threadIdx.x; i < Cc; i += blockDim.x)
        orow[i] = __float2half_rn((xr[i] - mean) * inv * g[i] + b[i]);
}

// ---------------------------------------------------------------------------
// Fused BN1 (per-t over B,C) + LN2 (per-row over C): writes x2 fp32 AND h fp16
// One block per t.
// ---------------------------------------------------------------------------
__global__ void bn_ln_kernel(const float* __restrict__ x1,
                             const float* __restrict__ bng, const float* __restrict__ bnb,
                             const float* __restrict__ lng, const float* __restrict__ lnb,
                             float* __restrict__ x2, __half* __restrict__ h) {
    int t = blockIdx.x;
    float s = 0.f, s2 = 0.f;
    for (int bi = 0; bi < Bb; bi++) {
        const float* xr = x1 + ((size_t)bi * Tt + t) * Cc;
        for (int c = threadIdx.x; c < Cc; c += blockDim.x) {
            float v = xr[c]; s += v; s2 += v * v;
        }
    }
    const float cnt = (float)(Bb * Cc);
    float S = blk_reduce_sum(s), S2 = blk_reduce_sum(s2);
    float mean = S / cnt;
    float var = S2 / cnt - mean * mean;
    float inv = rsqrtf(var + EPSF);
    float gg = bng[t], bv = bnb[t];

    for (int bi = 0; bi < Bb; bi++) {
        const float* xr = x1 + ((size_t)bi * Tt + t) * Cc;
        float* x2r = x2 + ((size_t)bi * Tt + t) * Cc;
        __half* hr = h + ((size_t)bi * Tt + t) * Cc;
        float ls = 0.f, ls2 = 0.f;
        for (int c = threadIdx.x; c < Cc; c += blockDim.x) {
            float y = (xr[c] - mean) * inv * gg + bv;
            x2r[c] = y;
            ls += y; ls2 += y * y;
        }
        float LS = blk_reduce_sum(ls), LS2 = blk_reduce_sum(ls2);
        float lm = LS * (1.0f / Cc);
        float lvar = LS2 * (1.0f / Cc) - lm * lm;
        float linv = rsqrtf(lvar + EPSF);
        for (int c = threadIdx.x; c < Cc; c += blockDim.x) {
            float y = x2r[c];
            hr[c] = __float2half_rn((y - lm) * linv * lng[c] + lnb[c]);
        }
    }
}

// ---------------------------------------------------------------------------
// BatchNorm (final, fp32 out)
// ---------------------------------------------------------------------------
__global__ void bn_kernel(const float* __restrict__ x, const float* __restrict__ g,
                          const float* __restrict__ bb, float* __restrict__ out) {
    int t = blockIdx.x;
    float s = 0.f, s2 = 0.f;
    for (int bi = 0; bi < Bb; bi++) {
        const float* xr = x + ((size_t)bi * Tt + t) * Cc;
        for (int c = threadIdx.x; c < Cc; c += blockDim.x) {
            float v = xr[c]; s += v; s2 += v * v;
        }
    }
    const float cnt = (float)(Bb * Cc);
    float S = blk_reduce_sum(s), S2 = blk_reduce_sum(s2);
    float mean = S / cnt;
    float var = S2 / cnt - mean * mean;
    float inv = rsqrtf(var + EPSF);
    float gg = g[t], bv = bb[t];
    for (int bi = 0; bi < Bb; bi++) {
        const float* xr = x + ((size_t)bi * Tt + t) * Cc;
        float* orow = out + ((size_t)bi * Tt + t) * Cc;
        for (int c = threadIdx.x; c < Cc; c += blockDim.x)
            orow[c] = (xr[c] - mean) * inv * gg + bv;
    }
}

// ---------------------------------------------------------------------------
// Causal row softmax on fp16 scores (fp32 math)
// ---------------------------------------------------------------------------
__global__ void softmax_h(__half* __restrict__ s) {
    int t = blockIdx.x;
    size_t z = blockIdx.y;
    __half* row = s + (z * Tt + t) * (size_t)Tt;
    int n = t + 1;
    float mx = -3.4e38f;
    for (int i = threadIdx.x; i < n; i += blockDim.x)
        mx = fmaxf(mx, __half2float(row[i]));
    mx = blk_reduce_max(mx);
    float se = 0.f;
    for (int i = threadIdx.x; i < n; i += blockDim.x)
        se += expf(__half2float(row[i]) - mx);
    se = blk_reduce_sum(se);
    float inv = 1.0f / se;
    for (int i = threadIdx.x; i < n; i += blockDim.x)
        row[i] = __float2half_rn(expf(__half2float(row[i]) - mx) * inv);
    for (int i = n + threadIdx.x; i < Tt; i += blockDim.x)
        row[i] = __float2half_rn(0.f);
}

// ---------------------------------------------------------------------------
// Launch
// ---------------------------------------------------------------------------
extern "C" void kernel_launch(void* const* d_in, const int* in_sizes, int n_in,
                              void* d_out, int out_size) {
    const float* x     = (const float*)d_in[0];
    const float* wq    = (const float*)d_in[1];
    const float* wk    = (const float*)d_in[2];
    const float* wv    = (const float*)d_in[3];
    const float* wo    = (const float*)d_in[4];
    const float* bo    = (const float*)d_in[5];
    const float* ln1_g = (const float*)d_in[6];
    const float* ln1_b = (const float*)d_in[7];
    const float* ln2_g = (const float*)d_in[8];
    const float* ln2_b = (const float*)d_in[9];
    const float* w1    = (const float*)d_in[10];
    const float* b1    = (const float*)d_in[11];
    const float* w2    = (const float*)d_in[12];
    const float* b2    = (const float*)d_in[13];
    const float* bn1_g = (const float*)d_in[14];
    const float* bn1_b = (const float*)d_in[15];
    const float* bn2_g = (const float*)d_in[16];
    const float* bn2_b = (const float*)d_in[17];
    float* out = (float*)d_out;

    __half *h, *qkv, *s, *o, *f1, *wqkvT, *woT, *w1T, *w2T, *vt;
    float *x1, *x2, *f2;
    cudaGetSymbolAddress((void**)&h,   g_h);
    cudaGetSymbolAddress((void**)&qkv, g_qkv);
    cudaGetSymbolAddress((void**)&s,   g_s);
    cudaGetSymbolAddress((void**)&o,   g_o);
    cudaGetSymbolAddress((void**)&f1,  g_f1);
    cudaGetSymbolAddress((void**)&wqkvT, g_wqkvT);
    cudaGetSymbolAddress((void**)&woT, g_woT);
    cudaGetSymbolAddress((void**)&w1T, g_w1T);
    cudaGetSymbolAddress((void**)&w2T, g_w2T);
    cudaGetSymbolAddress((void**)&vt,  g_vt);
    cudaGetSymbolAddress((void**)&x1, g_x1);
    cudaGetSymbolAddress((void**)&x2, g_x2);
    cudaGetSymbolAddress((void**)&f2, g_f2);

    const long long CD = (long long)Cc * Dd;
    const long long TC = (long long)Tt * Cc;
    const long long TT = (long long)Tt * Tt;
    const long long DT = (long long)Dd * Tt;
    const long long HDC = (long long)Hh * Dd * Cc;

    const __half* q = qkv;
    const __half* k = qkv + (size_t)BT * Cc;
    const __half* v = qkv + (size_t)2 * BT * Cc;

    cudaFuncSetAttribute(hgemm<128>, cudaFuncAttributeMaxDynamicSharedMemorySize, 4 * (128 * 80 + 128 * 80));
    cudaFuncSetAttribute(hgemm<256>, cudaFuncAttributeMaxDynamicSharedMemorySize, 4 * (256 * 80 + 128 * 80));
    const int SM128 = 4 * (128 * 80 + 128 * 80);   // 81920
    const int SM256 = 4 * (256 * 80 + 128 * 80);   // 122880

    // Launches 1-5 (ncu -s 5 skips these; 6th launch = QKV hgemm gets profiled)
    transpose_f2h<<<dim3(Dd / 32, Cc / 32, Hh), 256>>>(wq, wqkvT,           Dd, Cc, 1, CD, 0, CD, 0);
    transpose_f2h<<<dim3(Dd / 32, Cc / 32, Hh), 256>>>(wk, wqkvT + HDC,     Dd, Cc, 1, CD, 0, CD, 0);
    transpose_f2h<<<dim3(Dd / 32, Cc / 32, Hh), 256>>>(wv, wqkvT + 2 * HDC, Dd, Cc, 1, CD, 0, CD, 0);
    ln_kernel<<<BT, 256>>>(x, ln1_g, ln1_b, h);
    transpose_f2h<<<dim3(Cc / 32, Cc / 32, 1), 256>>>(wo, woT, Cc, Cc, 1, 0, 0, 0, 0);

    // 6. QKV fused: z = which*12 + head; M=8192, N=128, K=1536
    {
        dim3 g(1, BT / 256, 3 * Hh);
        hgemm<256><<<g, 256, SM256>>>(h, wqkvT, (void*)qkv, BT, Dd, Cc, Cc, Cc, Cc, 1.f,
                                      nullptr, nullptr, 0, 1, 0, 0, Hh,
                                      0, 0, HDC, CD, (long long)BT * Cc, (long long)Dd);
    }

    transpose_f2h<<<dim3(Ff / 32, Cc / 32, 1), 256>>>(w1, w1T, Ff, Cc, 1, 0, 0, 0, 0);
    transpose_f2h<<<dim3(Cc / 32, Ff / 32, 1), 256>>>(w2, w2T, Cc, Ff, 1, 0, 0, 0, 0);

    // v -> vT (per b,h: [T,D] -> [D,T])
    transpose_h2h<<<dim3(Dd / 32, Tt / 32, Bb * Hh), 256>>>(
        v, vt, Cc, Tt, Hh, TC, (long long)Dd, (long long)Hh * DT, DT);

    // scores = alpha * Q K^T — causal tile skip
    {
        dim3 g(Tt / 128, Tt / 128, Bb * Hh);
        hgemm<128><<<g, 256, SM128>>>(q, k, (void*)s, Tt, Tt, Dd, Cc, Cc, Tt,
                                      0.08838834764831843f,
                                      nullptr, nullptr, 0, 1, 1, 0, Hh,
                                      TC, (long long)Dd, TC, (long long)Dd,
                                      (long long)Hh * TT, TT);
    }

    softmax_h<<<dim3(Tt, Bb * Hh), 128>>>(s);

    // O = P V (K capped at diagonal)
    {
        dim3 g(1, Tt / 128, Bb * Hh);
        hgemm<128><<<g, 256, SM128>>>(s, vt, (void*)o, Tt, Dd, Tt, Tt, Tt, Cc, 1.f,
                                      nullptr, nullptr, 0, 1, 0, 1, Hh,
                                      (long long)Hh * TT, TT, (long long)Hh * DT, DT,
                                      TC, (long long)Dd);
    }

    // x1 = x + (O @ wo + bo)
    {
        dim3 g(Cc / 128, BT / 256, 1);
        hgemm<256><<<g, 256, SM256>>>(o, woT, x1, BT, Cc, Cc, Cc, Cc, Cc, 1.f,
                                      bo, x, 0, 0, 0, 0, 1, 0, 0, 0, 0, 0, 0);
    }

    // BN1 + LN2 fused -> x2 (fp32), h (fp16)
    bn_ln_kernel<<<Tt, 256>>>(x1, bn1_g, bn1_b, ln2_g, ln2_b, x2, h);

    // f1 = relu(h @ w1 + b1)
    {
        dim3 g(Ff / 128, BT / 256, 1);
        hgemm<256><<<g, 256, SM256>>>(h, w1T, (void*)f1, BT, Ff, Cc, Cc, Cc, Ff, 1.f,
                                      b1, nullptr, 1, 1, 0, 0, 1, 0, 0, 0, 0, 0, 0);
    }

    // f2 = x2 + (f1 @ w2 + b2)
    {
        dim3 g(Cc / 128, BT / 256, 1);
        hgemm<256><<<g, 256, SM256>>>(f1, w2T, f2, BT, Cc, Ff, Ff, Ff, Cc, 1.f,
                                      b2, x2, 0, 0, 0, 0, 1, 0, 0, 0, 0, 0, 0);
    }

    // bn2 -> out
    bn_kernel<<<Tt, 256>>>(f2, bn2_g, bn2_b, out);
}

// round 11
// speedup vs baseline: 1.1583x; 1.1583x over previous
#include <cuda_runtime.h>
#include <cuda_fp16.h>
#include <cstdint>

// Problem constants
#define Bb 8
#define Tt 1024
#define Cc 1536
#define Hh 12
#define Dd 128
#define Ff 6144          // 4*C
#define BT 8192          // B*T
#define EPSF 1e-5f

// hgemm pipeline: 4 stages, K-chunk 32
#define STG_BYTES 20480
#define SMEM_BYTES (4 * STG_BYTES)   // 81920

// flash-attn smem
#define FQ_ROWB 272u                  // 128 halves + pad (68 words, %32=4)
#define FV_ROWB 144u                  // 64 halves + pad  (36 words, %32=4)
#define FQ_BYTES (128u * FQ_ROWB)     // 34816
#define FK_BYTES (64u * FQ_ROWB)      // 17408
#define FV_BYTES (128u * FV_ROWB)     // 18432
#define FSTG (FK_BYTES + FV_BYTES)    // 35840
#define FSMEM (FQ_BYTES + 4u * FSTG)  // 178176

// ---------------------------------------------------------------------------
// Scratch
// ---------------------------------------------------------------------------
__device__ __align__(256) __half g_h   [(size_t)BT * Cc];
__device__ __align__(256) __half g_qkv [(size_t)3 * BT * Cc];
__device__ __align__(256) __half g_o   [(size_t)BT * Cc];
__device__ __align__(256) __half g_f1  [(size_t)BT * Ff];
__device__ __align__(256) __half g_wqkvT[(size_t)3 * Hh * Dd * Cc];
__device__ __align__(256) __half g_woT [(size_t)Cc * Cc];
__device__ __align__(256) __half g_w1T [(size_t)Ff * Cc];
__device__ __align__(256) __half g_w2T [(size_t)Cc * Ff];
__device__ __align__(256) __half g_vt  [(size_t)Bb * Hh * Dd * Tt];
__device__ float g_x1 [(size_t)BT * Cc];
__device__ float g_x2 [(size_t)BT * Cc];
__device__ float g_f2 [(size_t)BT * Cc];

// ---------------------------------------------------------------------------
// Baseline-PTX helpers
// ---------------------------------------------------------------------------
__device__ __forceinline__ uint32_t smem_u32(const void* p) {
    uint32_t a;
    asm("{ .reg .u64 t; cvta.to.shared.u64 t, %1; cvt.u32.u64 %0, t; }" : "=r"(a) : "l"(p));
    return a;
}
__device__ __forceinline__ void cp16(uint32_t saddr, const void* gptr) {
    asm volatile("cp.async.cg.shared.global [%0], [%1], 16;" :: "r"(saddr), "l"(gptr));
}
#define CP_COMMIT() asm volatile("cp.async.commit_group;" ::: "memory")
#define CP_WAIT(n)  asm volatile("cp.async.wait_group %0;" :: "n"(n) : "memory")

__device__ __forceinline__ void ldsm4(uint32_t& r0, uint32_t& r1, uint32_t& r2,
                                      uint32_t& r3, uint32_t addr) {
    asm volatile("ldmatrix.sync.aligned.m8n8.x4.shared.b16 {%0,%1,%2,%3}, [%4];"
                 : "=r"(r0), "=r"(r1), "=r"(r2), "=r"(r3) : "r"(addr));
}
__device__ __forceinline__ void mma_f16(float* c, const uint32_t* a, const uint32_t* b) {
    asm volatile(
        "mma.sync.aligned.m16n8k16.row.col.f32.f16.f16.f32 "
        "{%0,%1,%2,%3}, {%4,%5,%6,%7}, {%8,%9}, {%0,%1,%2,%3};"
        : "+f"(c[0]), "+f"(c[1]), "+f"(c[2]), "+f"(c[3])
        : "r"(a[0]), "r"(a[1]), "r"(a[2]), "r"(a[3]), "r"(b[0]), "r"(b[1]));
}

// ---------------------------------------------------------------------------
// fp16 NT GEMM (R8-proven): CTA 128x128, 8 warps (4Mx2N), K chunk 32, 4-stage.
// ---------------------------------------------------------------------------
__global__ __launch_bounds__(256, 2)
void hgemm(const __half* __restrict__ A, const __half* __restrict__ Bm,
           void* __restrict__ Cv, int M, int N, int K,
           int lda, int ldb, int ldc, float alpha,
           const float* __restrict__ bias, const float* __restrict__ addp,
           int doRelu, int outHalf, int zdiv,
           long long aO, long long aI, long long bO, long long bI,
           long long cO, long long cI) {
    int m0 = blockIdx.y * 128, n0 = blockIdx.x * 128;

    long long z = blockIdx.z;
    long long zo = z / zdiv, zi = z % zdiv;
    A  += zo * aO + zi * aI;
    Bm += zo * bO + zi * bI;
    size_t coff = (size_t)(zo * cO + zi * cI);
    const float* addb = addp ? addp + coff : nullptr;

    extern __shared__ __align__(16) char sm[];
    uint32_t sbase = smem_u32(sm);

    int tid = threadIdx.x, wid = tid >> 5, lane = tid & 31;
    int gid = lane >> 2, tig = lane & 3;
    int wm = (wid & 3) * 32, wn = (wid >> 2) * 64;

    int lrow = tid >> 1, lsel = tid & 1;
    const __half* aR = A + (size_t)(m0 + lrow) * lda + lsel * 16;
    const __half* bR = Bm + (size_t)(n0 + lrow) * ldb + lsel * 16;
    uint32_t dA = sbase + (uint32_t)(lrow * 80 + lsel * 32);
    uint32_t dB = dA + 10240u;

    int nch = K >> 5;
    auto issue = [&](int ch) {
        if (ch < nch) {
            uint32_t so = (uint32_t)(ch & 3) * STG_BYTES;
            int k0 = ch * 32;
            cp16(dA + so,      aR + k0);
            cp16(dA + so + 16, aR + k0 + 8);
            cp16(dB + so,      bR + k0);
            cp16(dB + so + 16, bR + k0 + 8);
        }
        CP_COMMIT();
    };

    int g8 = lane >> 3, l8 = lane & 7;
    uint32_t aoff = (uint32_t)((((g8 & 1) * 8 + l8) * 80) + (g8 >> 1) * 16);
    uint32_t boff = 10240u + (uint32_t)((((g8 >> 1) * 8 + l8) * 80) + (g8 & 1) * 16);

    float acc[2][8][4];
    #pragma unroll
    for (int i = 0; i < 2; i++)
        #pragma unroll
        for (int j = 0; j < 8; j++)
            #pragma unroll
            for (int r = 0; r < 4; r++) acc[i][j][r] = 0.f;

    issue(0); issue(1); issue(2);

    for (int ch = 0; ch < nch; ch++) {
        CP_WAIT(2);
        __syncthreads();
        issue(ch + 3);

        uint32_t stg = sbase + (uint32_t)(ch & 3) * STG_BYTES;
        uint32_t aw0 = stg + aoff + (uint32_t)(wm * 80);
        uint32_t aw1 = aw0 + 16u * 80u;
        uint32_t bw  = stg + boff + (uint32_t)(wn * 80);

        #pragma unroll
        for (int s = 0; s < 2; s++) {
            uint32_t a[2][4];
            ldsm4(a[0][0], a[0][1], a[0][2], a[0][3], aw0 + s * 32);
            ldsm4(a[1][0], a[1][1], a[1][2], a[1][3], aw1 + s * 32);
            uint32_t b[8][2];
            #pragma unroll
            for (int jj = 0; jj < 4; jj++) {
                uint32_t t0, t1, t2, t3;
                ldsm4(t0, t1, t2, t3, bw + (uint32_t)(jj * 16 * 80) + s * 32);
                b[2 * jj][0] = t0; b[2 * jj][1] = t1;
                b[2 * jj + 1][0] = t2; b[2 * jj + 1][1] = t3;
            }
            #pragma unroll
            for (int i = 0; i < 2; i++)
                #pragma unroll
                for (int j = 0; j < 8; j++)
                    mma_f16(acc[i][j], a[i], b[j]);
        }
    }

    #pragma unroll
    for (int i = 0; i < 2; i++) {
        #pragma unroll
        for (int j = 0; j < 8; j++) {
            int r0 = m0 + wm + i * 16 + gid;
            int c  = n0 + wn + j * 8 + 2 * tig;
            #pragma unroll
            for (int hh = 0; hh < 2; hh++) {
                int r = r0 + hh * 8;
                float v0 = acc[i][j][2 * hh + 0] * alpha;
                float v1 = acc[i][j][2 * hh + 1] * alpha;
                if (bias) { v0 += bias[c]; v1 += bias[c + 1]; }
                if (doRelu) { v0 = fmaxf(v0, 0.f); v1 = fmaxf(v1, 0.f); }
                if (addb) {
                    const float* ap = addb + (size_t)r * ldc + c;
                    v0 += ap[0]; v1 += ap[1];
                }
                if (outHalf) {
                    __half2* cp = (__half2*)((__half*)Cv + coff + (size_t)r * ldc + c);
                    *cp = __floats2half2_rn(v0, v1);
                } else {
                    float2* cp = (float2*)((float*)Cv + coff + (size_t)r * ldc + c);
                    *cp = make_float2(v0, v1);
                }
            }
        }
    }
}

// ---------------------------------------------------------------------------
// Fused flash attention: one CTA per (qtile, b*H+h). 8 warps x m16.
// K-tiles of 64, 4-stage cp.async. Q tile loaded once. Causal, online softmax.
// q,k: [B,T,C] fp16 (head offset). vt: [b*h][D][T] fp16. o: [B,T,C] fp16.
// ---------------------------------------------------------------------------
__global__ __launch_bounds__(256, 1)
void flash_attn(const __half* __restrict__ qg, const __half* __restrict__ kg,
                const __half* __restrict__ vtg, __half* __restrict__ og) {
    extern __shared__ __align__(16) char sm[];
    uint32_t sb = smem_u32(sm);
    int qt = blockIdx.x;
    int z = blockIdx.y;
    int bi = z / Hh, hi = z % Hh;
    const __half* qb = qg + (size_t)bi * Tt * Cc + hi * Dd;
    const __half* kb = kg + (size_t)bi * Tt * Cc + hi * Dd;
    const __half* vb = vtg + (size_t)z * Dd * Tt;
    __half* ob = og + (size_t)bi * Tt * Cc + hi * Dd;

    int tid = threadIdx.x, wid = tid >> 5, lane = tid & 31;
    int gid = lane >> 2, tig = lane & 3;
    int g8 = lane >> 3, l8 = lane & 7;
    int wr = wid * 16;
    int nkt = 2 * qt + 2;

    // Q tile once (group 0 with KV0)
    #pragma unroll
    for (int i = 0; i < 8; i++) {
        int c = tid + i * 256;
        int r = c >> 4, q16 = c & 15;
        cp16(sb + (uint32_t)r * FQ_ROWB + (uint32_t)q16 * 16,
             qb + (size_t)(qt * 128 + r) * Cc + q16 * 8);
    }
    auto issueKV = [&](int kt) {
        if (kt < nkt) {
            uint32_t so = sb + FQ_BYTES + (uint32_t)(kt & 3) * FSTG;
            #pragma unroll
            for (int i = 0; i < 4; i++) {           // K: 64 rows x 256B
                int c = tid + i * 256;
                int r = c >> 4, q16 = c & 15;
                cp16(so + (uint32_t)r * FQ_ROWB + (uint32_t)q16 * 16,
                     kb + (size_t)(kt * 64 + r) * Cc + q16 * 8);
            }
            #pragma unroll
            for (int i = 0; i < 4; i++) {           // Vt: 128 rows x 128B
                int c = tid + i * 256;
                int r = c >> 3, q8 = c & 7;
                cp16(so + FK_BYTES + (uint32_t)r * FV_ROWB + (uint32_t)q8 * 16,
                     vb + (size_t)r * Tt + kt * 64 + q8 * 8);
            }
        }
        CP_COMMIT();
    };

    issueKV(0); issueKV(1); issueKV(2);

    uint32_t qoff = sb + (uint32_t)((wr + (g8 & 1) * 8 + l8) * FQ_ROWB) + (uint32_t)(g8 >> 1) * 16;
    uint32_t koffB = (uint32_t)((((g8 >> 1) * 8 + l8)) * FQ_ROWB) + (uint32_t)(g8 & 1) * 16;
    uint32_t voffB = (uint32_t)((((g8 >> 1) * 8 + l8)) * FV_ROWB) + (uint32_t)(g8 & 1) * 16;

    float Oa[16][4];
    #pragma unroll
    for (int j = 0; j < 16; j++)
        #pragma unroll
        for (int r = 0; r < 4; r++) Oa[j][r] = 0.f;
    float m0v = -1e30f, m1v = -1e30f, l0 = 0.f, l1 = 0.f;

    int grow0 = qt * 128 + wr + gid;
    int grow1 = grow0 + 8;
    const float ALPHA = 0.08838834764831843f;

    for (int kt = 0; kt < nkt; kt++) {
        CP_WAIT(2);
        __syncthreads();
        issueKV(kt + 3);

        uint32_t stg = sb + FQ_BYTES + (uint32_t)(kt & 3) * FSTG;

        // S = Q K^T for this 64-col tile
        float S[8][4];
        #pragma unroll
        for (int j = 0; j < 8; j++) { S[j][0] = S[j][1] = S[j][2] = S[j][3] = 0.f; }
        #pragma unroll
        for (int ks = 0; ks < 8; ks++) {
            uint32_t aq[4];
            ldsm4(aq[0], aq[1], aq[2], aq[3], qoff + (uint32_t)ks * 32);
            uint32_t bk[8][2];
            #pragma unroll
            for (int jp = 0; jp < 4; jp++) {
                uint32_t t0, t1, t2, t3;
                ldsm4(t0, t1, t2, t3,
                      stg + koffB + (uint32_t)(jp * 16) * FQ_ROWB + (uint32_t)ks * 32);
                bk[2 * jp][0] = t0; bk[2 * jp][1] = t1;
                bk[2 * jp + 1][0] = t2; bk[2 * jp + 1][1] = t3;
            }
            #pragma unroll
            for (int j = 0; j < 8; j++) mma_f16(S[j], aq, bk[j]);
        }

        // mask + scale + online softmax
        int cbase = kt * 64;
        float mt0 = -1e30f, mt1 = -1e30f;
        #pragma unroll
        for (int j = 0; j < 8; j++) {
            int c0 = cbase + j * 8 + 2 * tig, c1 = c0 + 1;
            S[j][0] = (c0 <= grow0) ? S[j][0] * ALPHA : -1e30f;
            S[j][1] = (c1 <= grow0) ? S[j][1] * ALPHA : -1e30f;
            S[j][2] = (c0 <= grow1) ? S[j][2] * ALPHA : -1e30f;
            S[j][3] = (c1 <= grow1) ? S[j][3] * ALPHA : -1e30f;
            mt0 = fmaxf(mt0, fmaxf(S[j][0], S[j][1]));
            mt1 = fmaxf(mt1, fmaxf(S[j][2], S[j][3]));
        }
        mt0 = fmaxf(mt0, __shfl_xor_sync(0xffffffffu, mt0, 1));
        mt0 = fmaxf(mt0, __shfl_xor_sync(0xffffffffu, mt0, 2));
        mt1 = fmaxf(mt1, __shfl_xor_sync(0xffffffffu, mt1, 1));
        mt1 = fmaxf(mt1, __shfl_xor_sync(0xffffffffu, mt1, 2));
        float mn0 = fmaxf(m0v, mt0), mn1 = fmaxf(m1v, mt1);
        float f0 = __expf(m0v - mn0), f1 = __expf(m1v - mn1);
        m0v = mn0; m1v = mn1;
        float ps0 = 0.f, ps1 = 0.f;
        #pragma unroll
        for (int j = 0; j < 8; j++) {
            S[j][0] = __expf(S[j][0] - m0v);
            S[j][1] = __expf(S[j][1] - m0v);
            S[j][2] = __expf(S[j][2] - m1v);
            S[j][3] = __expf(S[j][3] - m1v);
            ps0 += S[j][0] + S[j][1];
            ps1 += S[j][2] + S[j][3];
        }
        ps0 += __shfl_xor_sync(0xffffffffu, ps0, 1);
        ps0 += __shfl_xor_sync(0xffffffffu, ps0, 2);
        ps1 += __shfl_xor_sync(0xffffffffu, ps1, 1);
        ps1 += __shfl_xor_sync(0xffffffffu, ps1, 2);
        l0 = l0 * f0 + ps0;
        l1 = l1 * f1 + ps1;
        #pragma unroll
        for (int j = 0; j < 16; j++) {
            Oa[j][0] *= f0; Oa[j][1] *= f0; Oa[j][2] *= f1; Oa[j][3] *= f1;
        }

        // O += P V : P (regs) x Vt tile
        #pragma unroll
        for (int jj = 0; jj < 4; jj++) {
            uint32_t aP[4];
            __half2 p0 = __floats2half2_rn(S[2 * jj][0], S[2 * jj][1]);
            __half2 p1 = __floats2half2_rn(S[2 * jj][2], S[2 * jj][3]);
            __half2 p2 = __floats2half2_rn(S[2 * jj + 1][0], S[2 * jj + 1][1]);
            __half2 p3 = __floats2half2_rn(S[2 * jj + 1][2], S[2 * jj + 1][3]);
            aP[0] = *(uint32_t*)&p0; aP[1] = *(uint32_t*)&p1;
            aP[2] = *(uint32_t*)&p2; aP[3] = *(uint32_t*)&p3;
            uint32_t bv[16][2];
            #pragma unroll
            for (int jp = 0; jp < 8; jp++) {
                uint32_t t0, t1, t2, t3;
                ldsm4(t0, t1, t2, t3,
                      stg + FK_BYTES + voffB + (uint32_t)(jp * 16) * FV_ROWB + (uint32_t)jj * 32);
                bv[2 * jp][0] = t0; bv[2 * jp][1] = t1;
                bv[2 * jp + 1][0] = t2; bv[2 * jp + 1][1] = t3;
            }
            #pragma unroll
            for (int dt = 0; dt < 16; dt++) mma_f16(Oa[dt], aP, bv[dt]);
        }
    }

    float il0 = 1.f / l0, il1 = 1.f / l1;
    #pragma unroll
    for (int dt = 0; dt < 16; dt++) {
        int d = dt * 8 + 2 * tig;
        *(__half2*)(ob + (size_t)grow0 * Cc + d) = __floats2half2_rn(Oa[dt][0] * il0, Oa[dt][1] * il0);
        *(__half2*)(ob + (size_t)grow1 * Cc + d) = __floats2half2_rn(Oa[dt][2] * il1, Oa[dt][3] * il1);
    }
}

// ---------------------------------------------------------------------------
// Tiled transposes
// ---------------------------------------------------------------------------
__global__ void transpose_f2h(const float* __restrict__ in, __half* __restrict__ out,
                              int ldi, int ldo, int zdiv,
                              long long iO, long long iI, long long oO, long long oI) {
    __shared__ float tile[32][33];
    long long z = blockIdx.z;
    in  += (z / zdiv) * iO + (z % zdiv) * iI;
    out += (z / zdiv) * oO + (z % zdiv) * oI;
    int r0 = blockIdx.y * 32, c0 = blockIdx.x * 32;
    int tx = threadIdx.x & 31, ty = threadIdx.x >> 5;
    #pragma unroll
    for (int i = ty; i < 32; i += 8)
        tile[i][tx] = in[(size_t)(r0 + i) * ldi + c0 + tx];
    __syncthreads();
    #pragma unroll
    for (int i = ty; i < 32; i += 8)
        out[(size_t)(c0 + i) * ldo + r0 + tx] = __float2half_rn(tile[tx][i]);
}

__global__ void transpose_h2h(const __half* __restrict__ in, __half* __restrict__ out,
                              int ldi, int ldo, int zdiv,
                              long long iO, long long iI, long long oO, long long oI) {
    __shared__ __half tile[32][33];
    long long z = blockIdx.z;
    in  += (z / zdiv) * iO + (z % zdiv) * iI;
    out += (z / zdiv) * oO + (z % zdiv) * oI;
    int r0 = blockIdx.y * 32, c0 = blockIdx.x * 32;
    int tx = threadIdx.x & 31, ty = threadIdx.x >> 5;
    #pragma unroll
    for (int i = ty; i < 32; i += 8)
        tile[i][tx] = in[(size_t)(r0 + i) * ldi + c0 + tx];
    __syncthreads();
    #pragma unroll
    for (int i = ty; i < 32; i += 8)
        out[(size_t)(c0 + i) * ldo + r0 + tx] = tile[tx][i];
}

// ---------------------------------------------------------------------------
// Block reductions
// ---------------------------------------------------------------------------
__device__ __forceinline__ float blk_reduce_sum(float v) {
    __shared__ float sh[32];
    __syncthreads();
    int lane = threadIdx.x & 31, w = threadIdx.x >> 5;
    #pragma unroll
    for (int o = 16; o > 0; o >>= 1) v += __shfl_down_sync(0xffffffffu, v, o);
    if (lane == 0) sh[w] = v;
    __syncthreads();
    int nw = blockDim.x >> 5;
    if (w == 0) {
        v = (lane < nw) ? sh[lane] : 0.f;
        #pragma unroll
        for (int o = 16; o > 0; o >>= 1) v += __shfl_down_sync(0xffffffffu, v, o);
        if (lane == 0) sh[0] = v;
    }
    __syncthreads();
    return sh[0];
}

// ---------------------------------------------------------------------------
// LayerNorm (fp32 stats, fp16 out)
// ---------------------------------------------------------------------------
__global__ void ln_kernel(const float* __restrict__ x, const float* __restrict__ g,
                          const float* __restrict__ b, __half* __restrict__ out) {
    size_t row = blockIdx.x;
    const float* xr = x + row * Cc;
    float s = 0.f, s2 = 0.f;
    for (int i = threadIdx.x; i < Cc; i += blockDim.x) {
        float v = xr[i]; s += v; s2 += v * v;
    }
    float S = blk_reduce_sum(s), S2 = blk_reduce_sum(s2);
    float mean = S * (1.0f / Cc);
    float var = S2 * (1.0f / Cc) - mean * mean;
    float inv = rsqrtf(var + EPSF);
    __half* orow = out + row * Cc;
    for (int i = threadIdx.x; i < Cc; i += blockDim.x)
        orow[i] = __float2half_rn((xr[i] - mean) * inv * g[i] + b[i]);
}

// ---------------------------------------------------------------------------
// Fused BN1 + LN2
// ---------------------------------------------------------------------------
__global__ void bn_ln_kernel(const float* __restrict__ x1,
                             const float* __restrict__ bng, const float* __restrict__ bnb,
                             const float* __restrict__ lng, const float* __restrict__ lnb,
                             float* __restrict__ x2, __half* __restrict__ h) {
    int t = blockIdx.x;
    float s = 0.f, s2 = 0.f;
    for (int bi = 0; bi < Bb; bi++) {
        const float* xr = x1 + ((size_t)bi * Tt + t) * Cc;
        for (int c = threadIdx.x; c < Cc; c += blockDim.x) {
            float v = xr[c]; s += v; s2 += v * v;
        }
    }
    const float cnt = (float)(Bb * Cc);
    float S = blk_reduce_sum(s), S2 = blk_reduce_sum(s2);
    float mean = S / cnt;
    float var = S2 / cnt - mean * mean;
    float inv = rsqrtf(var + EPSF);
    float gg = bng[t], bv = bnb[t];

    for (int bi = 0; bi < Bb; bi++) {
        const float* xr = x1 + ((size_t)bi * Tt + t) * Cc;
        float* x2r = x2 + ((size_t)bi * Tt + t) * Cc;
        __half* hr = h + ((size_t)bi * Tt + t) * Cc;
        float ls = 0.f, ls2 = 0.f;
        for (int c = threadIdx.x; c < Cc; c += blockDim.x) {
            float y = (xr[c] - mean) * inv * gg + bv;
            x2r[c] = y;
            ls += y; ls2 += y * y;
        }
        float LS = blk_reduce_sum(ls), LS2 = blk_reduce_sum(ls2);
        float lm = LS * (1.0f / Cc);
        float lvar = LS2 * (1.0f / Cc) - lm * lm;
        float linv = rsqrtf(lvar + EPSF);
        for (int c = threadIdx.x; c < Cc; c += blockDim.x) {
            float y = x2r[c];
            hr[c] = __float2half_rn((y - lm) * linv * lng[c] + lnb[c]);
        }
    }
}

// ---------------------------------------------------------------------------
// Final BatchNorm
// ---------------------------------------------------------------------------
__global__ void bn_kernel(const float* __restrict__ x, const float* __restrict__ g,
                          const float* __restrict__ bb, float* __restrict__ out) {
    int t = blockIdx.x;
    float s = 0.f, s2 = 0.f;
    for (int bi = 0; bi < Bb; bi++) {
        const float* xr = x + ((size_t)bi * Tt + t) * Cc;
        for (int c = threadIdx.x; c < Cc; c += blockDim.x) {
            float v = xr[c]; s += v; s2 += v * v;
        }
    }
    const float cnt = (float)(Bb * Cc);
    float S = blk_reduce_sum(s), S2 = blk_reduce_sum(s2);
    float mean = S / cnt;
    float var = S2 / cnt - mean * mean;
    float inv = rsqrtf(var + EPSF);
    float gg = g[t], bv = bb[t];
    for (int bi = 0; bi < Bb; bi++) {
        const float* xr = x + ((size_t)bi * Tt + t) * Cc;
        float* orow = out + ((size_t)bi * Tt + t) * Cc;
        for (int c = threadIdx.x; c < Cc; c += blockDim.x)
            orow[c] = (xr[c] - mean) * inv * gg + bv;
    }
}

// ---------------------------------------------------------------------------
// Launch
// ---------------------------------------------------------------------------
extern "C" void kernel_launch(void* const* d_in, const int* in_sizes, int n_in,
                              void* d_out, int out_size) {
    const float* x     = (const float*)d_in[0];
    const float* wq    = (const float*)d_in[1];
    const float* wk    = (const float*)d_in[2];
    const float* wv    = (const float*)d_in[3];
    const float* wo    = (const float*)d_in[4];
    const float* bo    = (const float*)d_in[5];
    const float* ln1_g = (const float*)d_in[6];
    const float* ln1_b = (const float*)d_in[7];
    const float* ln2_g = (const float*)d_in[8];
    const float* ln2_b = (const float*)d_in[9];
    const float* w1    = (const float*)d_in[10];
    const float* b1    = (const float*)d_in[11];
    const float* w2    = (const float*)d_in[12];
    const float* b2    = (const float*)d_in[13];
    const float* bn1_g = (const float*)d_in[14];
    const float* bn1_b = (const float*)d_in[15];
    const float* bn2_g = (const float*)d_in[16];
    const float* bn2_b = (const float*)d_in[17];
    float* out = (float*)d_out;

    __half *h, *qkv, *o, *f1, *wqkvT, *woT, *w1T, *w2T, *vt;
    float *x1, *x2, *f2;
    cudaGetSymbolAddress((void**)&h,   g_h);
    cudaGetSymbolAddress((void**)&qkv, g_qkv);
    cudaGetSymbolAddress((void**)&o,   g_o);
    cudaGetSymbolAddress((void**)&f1,  g_f1);
    cudaGetSymbolAddress((void**)&wqkvT, g_wqkvT);
    cudaGetSymbolAddress((void**)&woT, g_woT);
    cudaGetSymbolAddress((void**)&w1T, g_w1T);
    cudaGetSymbolAddress((void**)&w2T, g_w2T);
    cudaGetSymbolAddress((void**)&vt,  g_vt);
    cudaGetSymbolAddress((void**)&x1, g_x1);
    cudaGetSymbolAddress((void**)&x2, g_x2);
    cudaGetSymbolAddress((void**)&f2, g_f2);

    const long long CD = (long long)Cc * Dd;
    const long long TC = (long long)Tt * Cc;
    const long long DT = (long long)Dd * Tt;
    const long long HDC = (long long)Hh * Dd * Cc;

    const __half* q = qkv;
    const __half* k = qkv + (size_t)BT * Cc;
    const __half* v = qkv + (size_t)2 * BT * Cc;

    cudaFuncSetAttribute(hgemm, cudaFuncAttributeMaxDynamicSharedMemorySize, SMEM_BYTES);
    cudaFuncSetAttribute(flash_attn, cudaFuncAttributeMaxDynamicSharedMemorySize, FSMEM);

    // Launches 1-5; 6th = QKV hgemm (ncu -s 5 profiles it)
    transpose_f2h<<<dim3(Dd / 32, Cc / 32, Hh), 256>>>(wq, wqkvT,           Dd, Cc, 1, CD, 0, CD, 0);
    transpose_f2h<<<dim3(Dd / 32, Cc / 32, Hh), 256>>>(wk, wqkvT + HDC,     Dd, Cc, 1, CD, 0, CD, 0);
    transpose_f2h<<<dim3(Dd / 32, Cc / 32, Hh), 256>>>(wv, wqkvT + 2 * HDC, Dd, Cc, 1, CD, 0, CD, 0);
    ln_kernel<<<BT, 256>>>(x, ln1_g, ln1_b, h);
    transpose_f2h<<<dim3(Cc / 32, Cc / 32, 1), 256>>>(wo, woT, Cc, Cc, 1, 0, 0, 0, 0);

    // QKV fused: z = which*Hh + head
    {
        dim3 g(1, BT / 128, 3 * Hh);
        hgemm<<<g, 256, SMEM_BYTES>>>(h, wqkvT, (void*)qkv, BT, Dd, Cc, Cc, Cc, Cc, 1.f,
                                      nullptr, nullptr, 0, 1, Hh,
                                      0, 0, HDC, CD, (long long)BT * Cc, (long long)Dd);
    }

    transpose_f2h<<<dim3(Ff / 32, Cc / 32, 1), 256>>>(w1, w1T, Ff, Cc, 1, 0, 0, 0, 0);
    transpose_f2h<<<dim3(Cc / 32, Ff / 32, 1), 256>>>(w2, w2T, Cc, Ff, 1, 0, 0, 0, 0);

    // v -> vT (per b,h: [T,D] -> [D,T])
    transpose_h2h<<<dim3(Dd / 32, Tt / 32, Bb * Hh), 256>>>(
        v, vt, Cc, Tt, Hh, TC, (long long)Dd, (long long)Hh * DT, DT);

    // fused causal attention
    flash_attn<<<dim3(Tt / 128, Bb * Hh), 256, FSMEM>>>(q, k, vt, o);

    // x1 = x + (O @ wo + bo)
    {
        dim3 g(Cc / 128, BT / 128, 1);
        hgemm<<<g, 256, SMEM_BYTES>>>(o, woT, x1, BT, Cc, Cc, Cc, Cc, Cc, 1.f,
                                      bo, x, 0, 0, 1, 0, 0, 0, 0, 0, 0);
    }

    // BN1 + LN2 fused
    bn_ln_kernel<<<Tt, 256>>>(x1, bn1_g, bn1_b, ln2_g, ln2_b, x2, h);

    // f1 = relu(h @ w1 + b1)
    {
        dim3 g(Ff / 128, BT / 128, 1);
        hgemm<<<g, 256, SMEM_BYTES>>>(h, w1T, (void*)f1, BT, Ff, Cc, Cc, Cc, Ff, 1.f,
                                      b1, nullptr, 1, 1, 1, 0, 0, 0, 0, 0, 0);
    }

    // f2 = x2 + (f1 @ w2 + b2)
    {
        dim3 g(Cc / 128, BT / 128, 1);
        hgemm<<<g, 256, SMEM_BYTES>>>(f1, w2T, f2, BT, Cc, Ff, Ff, Ff, Cc, 1.f,
                                      b2, x2, 0, 0, 1, 0, 0, 0, 0, 0, 0);
    }

    // bn2 -> out
    bn_kernel<<<Tt, 256>>>(f2, bn2_g, bn2_b, out);
}

// round 12
// speedup vs baseline: 1.1993x; 1.0353x over previous
#include <cuda_runtime.h>
#include <cuda_fp16.h>
#include <cstdint>

// Problem constants
#define Bb 8
#define Tt 1024
#define Cc 1536
#define Hh 12
#define Dd 128
#define Ff 6144          // 4*C
#define BT 8192          // B*T
#define EPSF 1e-5f

// hgemm pipeline: 4 stages, K-chunk 32
#define STG_BYTES 20480
#define SMEM_BYTES (4 * STG_BYTES)   // 81920

// flash-attn smem (2-stage for 2 CTAs/SM)
#define FQ_ROWB 272u                  // 128 halves + pad
#define FV_ROWB 144u                  // 64 halves + pad
#define FQ_BYTES (128u * FQ_ROWB)     // 34816
#define FK_BYTES (64u * FQ_ROWB)      // 17408
#define FV_BYTES (128u * FV_ROWB)     // 18432
#define FSTG (FK_BYTES + FV_BYTES)    // 35840
#define FSMEM (FQ_BYTES + 2u * FSTG)  // 106496 -> 2 CTAs/SM

// ---------------------------------------------------------------------------
// Scratch
// ---------------------------------------------------------------------------
__device__ __align__(256) __half g_h   [(size_t)BT * Cc];
__device__ __align__(256) __half g_qkv [(size_t)3 * BT * Cc];
__device__ __align__(256) __half g_o   [(size_t)BT * Cc];
__device__ __align__(256) __half g_f1  [(size_t)BT * Ff];
__device__ __align__(256) __half g_wqkvT[(size_t)3 * Hh * Dd * Cc];
__device__ __align__(256) __half g_woT [(size_t)Cc * Cc];
__device__ __align__(256) __half g_w1T [(size_t)Ff * Cc];
__device__ __align__(256) __half g_w2T [(size_t)Cc * Ff];
__device__ __align__(256) __half g_vt  [(size_t)Bb * Hh * Dd * Tt];
__device__ float g_x1 [(size_t)BT * Cc];
__device__ float g_x2 [(size_t)BT * Cc];
__device__ float g_f2 [(size_t)BT * Cc];

// ---------------------------------------------------------------------------
// Baseline-PTX helpers
// ---------------------------------------------------------------------------
__device__ __forceinline__ uint32_t smem_u32(const void* p) {
    uint32_t a;
    asm("{ .reg .u64 t; cvta.to.shared.u64 t, %1; cvt.u32.u64 %0, t; }" : "=r"(a) : "l"(p));
    return a;
}
__device__ __forceinline__ void cp16(uint32_t saddr, const void* gptr) {
    asm volatile("cp.async.cg.shared.global [%0], [%1], 16;" :: "r"(saddr), "l"(gptr));
}
#define CP_COMMIT() asm volatile("cp.async.commit_group;" ::: "memory")
#define CP_WAIT(n)  asm volatile("cp.async.wait_group %0;" :: "n"(n) : "memory")

__device__ __forceinline__ void ldsm4(uint32_t& r0, uint32_t& r1, uint32_t& r2,
                                      uint32_t& r3, uint32_t addr) {
    asm volatile("ldmatrix.sync.aligned.m8n8.x4.shared.b16 {%0,%1,%2,%3}, [%4];"
                 : "=r"(r0), "=r"(r1), "=r"(r2), "=r"(r3) : "r"(addr));
}
__device__ __forceinline__ void mma_f16(float* c, const uint32_t* a, const uint32_t* b) {
    asm volatile(
        "mma.sync.aligned.m16n8k16.row.col.f32.f16.f16.f32 "
        "{%0,%1,%2,%3}, {%4,%5,%6,%7}, {%8,%9}, {%0,%1,%2,%3};"
        : "+f"(c[0]), "+f"(c[1]), "+f"(c[2]), "+f"(c[3])
        : "r"(a[0]), "r"(a[1]), "r"(a[2]), "r"(a[3]), "r"(b[0]), "r"(b[1]));
}

// ---------------------------------------------------------------------------
// fp16 NT GEMM (R8-proven): CTA 128x128, 8 warps (4Mx2N), K chunk 32, 4-stage.
// ---------------------------------------------------------------------------
__global__ __launch_bounds__(256, 2)
void hgemm(const __half* __restrict__ A, const __half* __restrict__ Bm,
           void* __restrict__ Cv, int M, int N, int K,
           int lda, int ldb, int ldc, float alpha,
           const float* __restrict__ bias, const float* __restrict__ addp,
           int doRelu, int outHalf, int zdiv,
           long long aO, long long aI, long long bO, long long bI,
           long long cO, long long cI) {
    int m0 = blockIdx.y * 128, n0 = blockIdx.x * 128;

    long long z = blockIdx.z;
    long long zo = z / zdiv, zi = z % zdiv;
    A  += zo * aO + zi * aI;
    Bm += zo * bO + zi * bI;
    size_t coff = (size_t)(zo * cO + zi * cI);
    const float* addb = addp ? addp + coff : nullptr;

    extern __shared__ __align__(16) char sm[];
    uint32_t sbase = smem_u32(sm);

    int tid = threadIdx.x, wid = tid >> 5, lane = tid & 31;
    int gid = lane >> 2, tig = lane & 3;
    int wm = (wid & 3) * 32, wn = (wid >> 2) * 64;

    int lrow = tid >> 1, lsel = tid & 1;
    const __half* aR = A + (size_t)(m0 + lrow) * lda + lsel * 16;
    const __half* bR = Bm + (size_t)(n0 + lrow) * ldb + lsel * 16;
    uint32_t dA = sbase + (uint32_t)(lrow * 80 + lsel * 32);
    uint32_t dB = dA + 10240u;

    int nch = K >> 5;
    auto issue = [&](int ch) {
        if (ch < nch) {
            uint32_t so = (uint32_t)(ch & 3) * STG_BYTES;
            int k0 = ch * 32;
            cp16(dA + so,      aR + k0);
            cp16(dA + so + 16, aR + k0 + 8);
            cp16(dB + so,      bR + k0);
            cp16(dB + so + 16, bR + k0 + 8);
        }
        CP_COMMIT();
    };

    int g8 = lane >> 3, l8 = lane & 7;
    uint32_t aoff = (uint32_t)((((g8 & 1) * 8 + l8) * 80) + (g8 >> 1) * 16);
    uint32_t boff = 10240u + (uint32_t)((((g8 >> 1) * 8 + l8) * 80) + (g8 & 1) * 16);

    float acc[2][8][4];
    #pragma unroll
    for (int i = 0; i < 2; i++)
        #pragma unroll
        for (int j = 0; j < 8; j++)
            #pragma unroll
            for (int r = 0; r < 4; r++) acc[i][j][r] = 0.f;

    issue(0); issue(1); issue(2);

    for (int ch = 0; ch < nch; ch++) {
        CP_WAIT(2);
        __syncthreads();
        issue(ch + 3);

        uint32_t stg = sbase + (uint32_t)(ch & 3) * STG_BYTES;
        uint32_t aw0 = stg + aoff + (uint32_t)(wm * 80);
        uint32_t aw1 = aw0 + 16u * 80u;
        uint32_t bw  = stg + boff + (uint32_t)(wn * 80);

        #pragma unroll
        for (int s = 0; s < 2; s++) {
            uint32_t a[2][4];
            ldsm4(a[0][0], a[0][1], a[0][2], a[0][3], aw0 + s * 32);
            ldsm4(a[1][0], a[1][1], a[1][2], a[1][3], aw1 + s * 32);
            uint32_t b[8][2];
            #pragma unroll
            for (int jj = 0; jj < 4; jj++) {
                uint32_t t0, t1, t2, t3;
                ldsm4(t0, t1, t2, t3, bw + (uint32_t)(jj * 16 * 80) + s * 32);
                b[2 * jj][0] = t0; b[2 * jj][1] = t1;
                b[2 * jj + 1][0] = t2; b[2 * jj + 1][1] = t3;
            }
            #pragma unroll
            for (int i = 0; i < 2; i++)
                #pragma unroll
                for (int j = 0; j < 8; j++)
                    mma_f16(acc[i][j], a[i], b[j]);
        }
    }

    #pragma unroll
    for (int i = 0; i < 2; i++) {
        #pragma unroll
        for (int j = 0; j < 8; j++) {
            int r0 = m0 + wm + i * 16 + gid;
            int c  = n0 + wn + j * 8 + 2 * tig;
            #pragma unroll
            for (int hh = 0; hh < 2; hh++) {
                int r = r0 + hh * 8;
                float v0 = acc[i][j][2 * hh + 0] * alpha;
                float v1 = acc[i][j][2 * hh + 1] * alpha;
                if (bias) { v0 += bias[c]; v1 += bias[c + 1]; }
                if (doRelu) { v0 = fmaxf(v0, 0.f); v1 = fmaxf(v1, 0.f); }
                if (addb) {
                    const float* ap = addb + (size_t)r * ldc + c;
                    v0 += ap[0]; v1 += ap[1];
                }
                if (outHalf) {
                    __half2* cp = (__half2*)((__half*)Cv + coff + (size_t)r * ldc + c);
                    *cp = __floats2half2_rn(v0, v1);
                } else {
                    float2* cp = (float2*)((float*)Cv + coff + (size_t)r * ldc + c);
                    *cp = make_float2(v0, v1);
                }
            }
        }
    }
}

// ---------------------------------------------------------------------------
// Fused flash attention: 2-stage pipeline, 2 CTAs/SM, heavy tiles first.
// ---------------------------------------------------------------------------
__global__ __launch_bounds__(256, 2)
void flash_attn(const __half* __restrict__ qg, const __half* __restrict__ kg,
                const __half* __restrict__ vtg, __half* __restrict__ og) {
    extern __shared__ __align__(16) char sm[];
    uint32_t sb = smem_u32(sm);
    int qt = gridDim.x - 1 - blockIdx.x;    // heavy (large-qt) tiles first
    int z = blockIdx.y;
    int bi = z / Hh, hi = z % Hh;
    const __half* qb = qg + (size_t)bi * Tt * Cc + hi * Dd;
    const __half* kb = kg + (size_t)bi * Tt * Cc + hi * Dd;
    const __half* vb = vtg + (size_t)z * Dd * Tt;
    __half* ob = og + (size_t)bi * Tt * Cc + hi * Dd;

    int tid = threadIdx.x, wid = tid >> 5, lane = tid & 31;
    int gid = lane >> 2, tig = lane & 3;
    int g8 = lane >> 3, l8 = lane & 7;
    int wr = wid * 16;
    int nkt = 2 * qt + 2;

    // Q tile once (bundled into first commit group)
    #pragma unroll
    for (int i = 0; i < 8; i++) {
        int c = tid + i * 256;
        int r = c >> 4, q16 = c & 15;
        cp16(sb + (uint32_t)r * FQ_ROWB + (uint32_t)q16 * 16,
             qb + (size_t)(qt * 128 + r) * Cc + q16 * 8);
    }
    auto issueKV = [&](int kt) {
        if (kt < nkt) {
            uint32_t so = sb + FQ_BYTES + (uint32_t)(kt & 1) * FSTG;
            #pragma unroll
            for (int i = 0; i < 4; i++) {           // K: 64 rows x 256B
                int c = tid + i * 256;
                int r = c >> 4, q16 = c & 15;
                cp16(so + (uint32_t)r * FQ_ROWB + (uint32_t)q16 * 16,
                     kb + (size_t)(kt * 64 + r) * Cc + q16 * 8);
            }
            #pragma unroll
            for (int i = 0; i < 4; i++) {           // Vt: 128 rows x 128B
                int c = tid + i * 256;
                int r = c >> 3, q8 = c & 7;
                cp16(so + FK_BYTES + (uint32_t)r * FV_ROWB + (uint32_t)q8 * 16,
                     vb + (size_t)r * Tt + kt * 64 + q8 * 8);
            }
        }
        CP_COMMIT();
    };

    issueKV(0); issueKV(1);

    uint32_t qoff = sb + (uint32_t)((wr + (g8 & 1) * 8 + l8) * FQ_ROWB) + (uint32_t)(g8 >> 1) * 16;
    uint32_t koffB = (uint32_t)((((g8 >> 1) * 8 + l8)) * FQ_ROWB) + (uint32_t)(g8 & 1) * 16;
    uint32_t voffB = (uint32_t)((((g8 >> 1) * 8 + l8)) * FV_ROWB) + (uint32_t)(g8 & 1) * 16;

    float Oa[16][4];
    #pragma unroll
    for (int j = 0; j < 16; j++)
        #pragma unroll
        for (int r = 0; r < 4; r++) Oa[j][r] = 0.f;
    float m0v = -1e30f, m1v = -1e30f, l0 = 0.f, l1 = 0.f;

    int grow0 = qt * 128 + wr + gid;
    int grow1 = grow0 + 8;
    const float ALPHA = 0.08838834764831843f;

    for (int kt = 0; kt < nkt; kt++) {
        CP_WAIT(1);
        __syncthreads();

        uint32_t stg = sb + FQ_BYTES + (uint32_t)(kt & 1) * FSTG;

        // S = Q K^T for this 64-col tile
        float S[8][4];
        #pragma unroll
        for (int j = 0; j < 8; j++) { S[j][0] = S[j][1] = S[j][2] = S[j][3] = 0.f; }
        #pragma unroll
        for (int ks = 0; ks < 8; ks++) {
            uint32_t aq[4];
            ldsm4(aq[0], aq[1], aq[2], aq[3], qoff + (uint32_t)ks * 32);
            uint32_t bk[8][2];
            #pragma unroll
            for (int jp = 0; jp < 4; jp++) {
                uint32_t t0, t1, t2, t3;
                ldsm4(t0, t1, t2, t3,
                      stg + koffB + (uint32_t)(jp * 16) * FQ_ROWB + (uint32_t)ks * 32);
                bk[2 * jp][0] = t0; bk[2 * jp][1] = t1;
                bk[2 * jp + 1][0] = t2; bk[2 * jp + 1][1] = t3;
            }
            #pragma unroll
            for (int j = 0; j < 8; j++) mma_f16(S[j], aq, bk[j]);
        }

        // mask + scale + online softmax
        int cbase = kt * 64;
        float mt0 = -1e30f, mt1 = -1e30f;
        #pragma unroll
        for (int j = 0; j < 8; j++) {
            int c0 = cbase + j * 8 + 2 * tig, c1 = c0 + 1;
            S[j][0] = (c0 <= grow0) ? S[j][0] * ALPHA : -1e30f;
            S[j][1] = (c1 <= grow0) ? S[j][1] * ALPHA : -1e30f;
            S[j][2] = (c0 <= grow1) ? S[j][2] * ALPHA : -1e30f;
            S[j][3] = (c1 <= grow1) ? S[j][3] * ALPHA : -1e30f;
            mt0 = fmaxf(mt0, fmaxf(S[j][0], S[j][1]));
            mt1 = fmaxf(mt1, fmaxf(S[j][2], S[j][3]));
        }
        mt0 = fmaxf(mt0, __shfl_xor_sync(0xffffffffu, mt0, 1));
        mt0 = fmaxf(mt0, __shfl_xor_sync(0xffffffffu, mt0, 2));
        mt1 = fmaxf(mt1, __shfl_xor_sync(0xffffffffu, mt1, 1));
        mt1 = fmaxf(mt1, __shfl_xor_sync(0xffffffffu, mt1, 2));
        float mn0 = fmaxf(m0v, mt0), mn1 = fmaxf(m1v, mt1);
        float f0 = __expf(m0v - mn0), f1 = __expf(m1v - mn1);
        m0v = mn0; m1v = mn1;
        float ps0 = 0.f, ps1 = 0.f;
        #pragma unroll
        for (int j = 0; j < 8; j++) {
            S[j][0] = __expf(S[j][0] - m0v);
            S[j][1] = __expf(S[j][1] - m0v);
            S[j][2] = __expf(S[j][2] - m1v);
            S[j][3] = __expf(S[j][3] - m1v);
            ps0 += S[j][0] + S[j][1];
            ps1 += S[j][2] + S[j][3];
        }
        ps0 += __shfl_xor_sync(0xffffffffu, ps0, 1);
        ps0 += __shfl_xor_sync(0xffffffffu, ps0, 2);
        ps1 += __shfl_xor_sync(0xffffffffu, ps1, 1);
        ps1 += __shfl_xor_sync(0xffffffffu, ps1, 2);
        l0 = l0 * f0 + ps0;
        l1 = l1 * f1 + ps1;
        #pragma unroll
        for (int j = 0; j < 16; j++) {
            Oa[j][0] *= f0; Oa[j][1] *= f0; Oa[j][2] *= f1; Oa[j][3] *= f1;
        }

        // O += P V
        #pragma unroll
        for (int jj = 0; jj < 4; jj++) {
            uint32_t aP[4];
            __half2 p0 = __floats2half2_rn(S[2 * jj][0], S[2 * jj][1]);
            __half2 p1 = __floats2half2_rn(S[2 * jj][2], S[2 * jj][3]);
            __half2 p2 = __floats2half2_rn(S[2 * jj + 1][0], S[2 * jj + 1][1]);
            __half2 p3 = __floats2half2_rn(S[2 * jj + 1][2], S[2 * jj + 1][3]);
            aP[0] = *(uint32_t*)&p0; aP[1] = *(uint32_t*)&p1;
            aP[2] = *(uint32_t*)&p2; aP[3] = *(uint32_t*)&p3;
            uint32_t bv[16][2];
            #pragma unroll
            for (int jp = 0; jp < 8; jp++) {
                uint32_t t0, t1, t2, t3;
                ldsm4(t0, t1, t2, t3,
                      stg + FK_BYTES + voffB + (uint32_t)(jp * 16) * FV_ROWB + (uint32_t)jj * 32);
                bv[2 * jp][0] = t0; bv[2 * jp][1] = t1;
                bv[2 * jp + 1][0] = t2; bv[2 * jp + 1][1] = t3;
            }
            #pragma unroll
            for (int dt = 0; dt < 16; dt++) mma_f16(Oa[dt], aP, bv[dt]);
        }

        __syncthreads();          // all warps done with stage (kt&1)
        issueKV(kt + 2);          // refill same buffer
    }

    float il0 = 1.f / l0, il1 = 1.f / l1;
    #pragma unroll
    for (int dt = 0; dt < 16; dt++) {
        int d = dt * 8 + 2 * tig;
        *(__half2*)(ob + (size_t)grow0 * Cc + d) = __floats2half2_rn(Oa[dt][0] * il0, Oa[dt][1] * il0);
        *(__half2*)(ob + (size_t)grow1 * Cc + d) = __floats2half2_rn(Oa[dt][2] * il1, Oa[dt][3] * il1);
    }
}

// ---------------------------------------------------------------------------
// Tiled transposes
// ---------------------------------------------------------------------------
__global__ void transpose_f2h(const float* __restrict__ in, __half* __restrict__ out,
                              int ldi, int ldo, int zdiv,
                              long long iO, long long iI, long long oO, long long oI) {
    __shared__ float tile[32][33];
    long long z = blockIdx.z;
    in  += (z / zdiv) * iO + (z % zdiv) * iI;
    out += (z / zdiv) * oO + (z % zdiv) * oI;
    int r0 = blockIdx.y * 32, c0 = blockIdx.x * 32;
    int tx = threadIdx.x & 31, ty = threadIdx.x >> 5;
    #pragma unroll
    for (int i = ty; i < 32; i += 8)
        tile[i][tx] = in[(size_t)(r0 + i) * ldi + c0 + tx];
    __syncthreads();
    #pragma unroll
    for (int i = ty; i < 32; i += 8)
        out[(size_t)(c0 + i) * ldo + r0 + tx] = __float2half_rn(tile[tx][i]);
}

__global__ void transpose_h2h(const __half* __restrict__ in, __half* __restrict__ out,
                              int ldi, int ldo, int zdiv,
                              long long iO, long long iI, long long oO, long long oI) {
    __shared__ __half tile[32][33];
    long long z = blockIdx.z;
    in  += (z / zdiv) * iO + (z % zdiv) * iI;
    out += (z / zdiv) * oO + (z % zdiv) * oI;
    int r0 = blockIdx.y * 32, c0 = blockIdx.x * 32;
    int tx = threadIdx.x & 31, ty = threadIdx.x >> 5;
    #pragma unroll
    for (int i = ty; i < 32; i += 8)
        tile[i][tx] = in[(size_t)(r0 + i) * ldi + c0 + tx];
    __syncthreads();
    #pragma unroll
    for (int i = ty; i < 32; i += 8)
        out[(size_t)(c0 + i) * ldo + r0 + tx] = tile[tx][i];
}

// ---------------------------------------------------------------------------
// Paired block reduction (sum of two values, one barrier tree)
// ---------------------------------------------------------------------------
__device__ __forceinline__ void blk_reduce_sum2(float& a, float& b) {
    __shared__ float2 sh[32];
    __syncthreads();
    int lane = threadIdx.x & 31, w = threadIdx.x >> 5;
    #pragma unroll
    for (int o = 16; o > 0; o >>= 1) {
        a += __shfl_down_sync(0xffffffffu, a, o);
        b += __shfl_down_sync(0xffffffffu, b, o);
    }
    if (lane == 0) sh[w] = make_float2(a, b);
    __syncthreads();
    int nw = blockDim.x >> 5;
    if (w == 0) {
        float2 v = (lane < nw) ? sh[lane] : make_float2(0.f, 0.f);
        a = v.x; b = v.y;
        #pragma unroll
        for (int o = 16; o > 0; o >>= 1) {
            a += __shfl_down_sync(0xffffffffu, a, o);
            b += __shfl_down_sync(0xffffffffu, b, o);
        }
        if (lane == 0) sh[0] = make_float2(a, b);
    }
    __syncthreads();
    float2 r = sh[0];
    a = r.x; b = r.y;
}

// ---------------------------------------------------------------------------
// LayerNorm: register-cached, float2 vectorized. 256 thr, 3 float2 each.
// ---------------------------------------------------------------------------
__global__ void ln_kernel(const float* __restrict__ x, const float* __restrict__ g,
                          const float* __restrict__ b, __half* __restrict__ out) {
    size_t row = blockIdx.x;
    const float2* xr = (const float2*)(x + row * Cc);
    float2 xv[3];
    float s = 0.f, s2 = 0.f;
    #pragma unroll
    for (int j = 0; j < 3; j++) {
        xv[j] = xr[threadIdx.x + j * 256];
        s += xv[j].x + xv[j].y;
        s2 += xv[j].x * xv[j].x + xv[j].y * xv[j].y;
    }
    blk_reduce_sum2(s, s2);
    float mean = s * (1.0f / Cc);
    float var = s2 * (1.0f / Cc) - mean * mean;
    float inv = rsqrtf(var + EPSF);
    __half2* orow = (__half2*)(out + row * Cc);
    const float2* g2 = (const float2*)g;
    const float2* b2 = (const float2*)b;
    #pragma unroll
    for (int j = 0; j < 3; j++) {
        int idx = threadIdx.x + j * 256;
        float2 gg = g2[idx], bb = b2[idx];
        orow[idx] = __floats2half2_rn((xv[j].x - mean) * inv * gg.x + bb.x,
                                      (xv[j].y - mean) * inv * gg.y + bb.y);
    }
}

// ---------------------------------------------------------------------------
// Fused BN1 + LN2: register-cached (24 float2/thread), single x1 read.
// ---------------------------------------------------------------------------
__global__ void bn_ln_kernel(const float* __restrict__ x1,
                             const float* __restrict__ bng, const float* __restrict__ bnb,
                             const float* __restrict__ lng, const float* __restrict__ lnb,
                             float* __restrict__ x2, __half* __restrict__ h) {
    int t = blockIdx.x;
    float2 xv[Bb][3];
    float s = 0.f, s2 = 0.f;
    #pragma unroll
    for (int bi = 0; bi < Bb; bi++) {
        const float2* xr = (const float2*)(x1 + ((size_t)bi * Tt + t) * Cc);
        #pragma unroll
        for (int j = 0; j < 3; j++) {
            xv[bi][j] = xr[threadIdx.x + j * 256];
            s += xv[bi][j].x + xv[bi][j].y;
            s2 += xv[bi][j].x * xv[bi][j].x + xv[bi][j].y * xv[bi][j].y;
        }
    }
    const float cnt = (float)(Bb * Cc);
    blk_reduce_sum2(s, s2);
    float mean = s / cnt;
    float var = s2 / cnt - mean * mean;
    float inv = rsqrtf(var + EPSF);
    float gg = bng[t], bv = bnb[t];

    const float2* lg2 = (const float2*)lng;
    const float2* lb2 = (const float2*)lnb;
    #pragma unroll
    for (int bi = 0; bi < Bb; bi++) {
        float2* x2r = (float2*)(x2 + ((size_t)bi * Tt + t) * Cc);
        __half2* hr = (__half2*)(h + ((size_t)bi * Tt + t) * Cc);
        float ls = 0.f, ls2 = 0.f;
        #pragma unroll
        for (int j = 0; j < 3; j++) {
            float yx = (xv[bi][j].x - mean) * inv * gg + bv;
            float yy = (xv[bi][j].y - mean) * inv * gg + bv;
            xv[bi][j] = make_float2(yx, yy);
            x2r[threadIdx.x + j * 256] = xv[bi][j];
            ls += yx + yy; ls2 += yx * yx + yy * yy;
        }
        blk_reduce_sum2(ls, ls2);
        float lm = ls * (1.0f / Cc);
        float lvar = ls2 * (1.0f / Cc) - lm * lm;
        float linv = rsqrtf(lvar + EPSF);
        #pragma unroll
        for (int j = 0; j < 3; j++) {
            int idx = threadIdx.x + j * 256;
            float2 lg = lg2[idx], lb = lb2[idx];
            hr[idx] = __floats2half2_rn((xv[bi][j].x - lm) * linv * lg.x + lb.x,
                                        (xv[bi][j].y - lm) * linv * lg.y + lb.y);
        }
    }
}

// ---------------------------------------------------------------------------
// Final BatchNorm: register-cached, single read.
// ---------------------------------------------------------------------------
__global__ void bn_kernel(const float* __restrict__ x, const float* __restrict__ g,
                          const float* __restrict__ bb, float* __restrict__ out) {
    int t = blockIdx.x;
    float2 xv[Bb][3];
    float s = 0.f, s2 = 0.f;
    #pragma unroll
    for (int bi = 0; bi < Bb; bi++) {
        const float2* xr = (const float2*)(x + ((size_t)bi * Tt + t) * Cc);
        #pragma unroll
        for (int j = 0; j < 3; j++) {
            xv[bi][j] = xr[threadIdx.x + j * 256];
            s += xv[bi][j].x + xv[bi][j].y;
            s2 += xv[bi][j].x * xv[bi][j].x + xv[bi][j].y * xv[bi][j].y;
        }
    }
    const float cnt = (float)(Bb * Cc);
    blk_reduce_sum2(s, s2);
    float mean = s / cnt;
    float var = s2 / cnt - mean * mean;
    float inv = rsqrtf(var + EPSF);
    float gg = g[t], bv = bb[t];
    #pragma unroll
    for (int bi = 0; bi < Bb; bi++) {
        float2* orow = (float2*)(out + ((size_t)bi * Tt + t) * Cc);
        #pragma unroll
        for (int j = 0; j < 3; j++)
            orow[threadIdx.x + j * 256] =
                make_float2((xv[bi][j].x - mean) * inv * gg + bv,
                            (xv[bi][j].y - mean) * inv * gg + bv);
    }
}

// ---------------------------------------------------------------------------
// Launch
// ---------------------------------------------------------------------------
extern "C" void kernel_launch(void* const* d_in, const int* in_sizes, int n_in,
                              void* d_out, int out_size) {
    const float* x     = (const float*)d_in[0];
    const float* wq    = (const float*)d_in[1];
    const float* wk    = (const float*)d_in[2];
    const float* wv    = (const float*)d_in[3];
    const float* wo    = (const float*)d_in[4];
    const float* bo    = (const float*)d_in[5];
    const float* ln1_g = (const float*)d_in[6];
    const float* ln1_b = (const float*)d_in[7];
    const float* ln2_g = (const float*)d_in[8];
    const float* ln2_b = (const float*)d_in[9];
    const float* w1    = (const float*)d_in[10];
    const float* b1    = (const float*)d_in[11];
    const float* w2    = (const float*)d_in[12];
    const float* b2    = (const float*)d_in[13];
    const float* bn1_g = (const float*)d_in[14];
    const float* bn1_b = (const float*)d_in[15];
    const float* bn2_g = (const float*)d_in[16];
    const float* bn2_b = (const float*)d_in[17];
    float* out = (float*)d_out;

    __half *h, *qkv, *o, *f1, *wqkvT, *woT, *w1T, *w2T, *vt;
    float *x1, *x2, *f2;
    cudaGetSymbolAddress((void**)&h,   g_h);
    cudaGetSymbolAddress((void**)&qkv, g_qkv);
    cudaGetSymbolAddress((void**)&o,   g_o);
    cudaGetSymbolAddress((void**)&f1,  g_f1);
    cudaGetSymbolAddress((void**)&wqkvT, g_wqkvT);
    cudaGetSymbolAddress((void**)&woT, g_woT);
    cudaGetSymbolAddress((void**)&w1T, g_w1T);
    cudaGetSymbolAddress((void**)&w2T, g_w2T);
    cudaGetSymbolAddress((void**)&vt,  g_vt);
    cudaGetSymbolAddress((void**)&x1, g_x1);
    cudaGetSymbolAddress((void**)&x2, g_x2);
    cudaGetSymbolAddress((void**)&f2, g_f2);

    const long long CD = (long long)Cc * Dd;
    const long long TC = (long long)Tt * Cc;
    const long long DT = (long long)Dd * Tt;
    const long long HDC = (long long)Hh * Dd * Cc;

    const __half* q = qkv;
    const __half* k = qkv + (size_t)BT * Cc;
    const __half* v = qkv + (size_t)2 * BT * Cc;

    cudaFuncSetAttribute(hgemm, cudaFuncAttributeMaxDynamicSharedMemorySize, SMEM_BYTES);
    cudaFuncSetAttribute(flash_attn, cudaFuncAttributeMaxDynamicSharedMemorySize, FSMEM);

    transpose_f2h<<<dim3(Dd / 32, Cc / 32, Hh), 256>>>(wq, wqkvT,           Dd, Cc, 1, CD, 0, CD, 0);
    transpose_f2h<<<dim3(Dd / 32, Cc / 32, Hh), 256>>>(wk, wqkvT + HDC,     Dd, Cc, 1, CD, 0, CD, 0);
    transpose_f2h<<<dim3(Dd / 32, Cc / 32, Hh), 256>>>(wv, wqkvT + 2 * HDC, Dd, Cc, 1, CD, 0, CD, 0);
    ln_kernel<<<BT, 256>>>(x, ln1_g, ln1_b, h);
    transpose_f2h<<<dim3(Cc / 32, Cc / 32, 1), 256>>>(wo, woT, Cc, Cc, 1, 0, 0, 0, 0);

    // QKV fused: z = which*Hh + head
    {
        dim3 g(1, BT / 128, 3 * Hh);
        hgemm<<<g, 256, SMEM_BYTES>>>(h, wqkvT, (void*)qkv, BT, Dd, Cc, Cc, Cc, Cc, 1.f,
                                      nullptr, nullptr, 0, 1, Hh,
                                      0, 0, HDC, CD, (long long)BT * Cc, (long long)Dd);
    }

    transpose_f2h<<<dim3(Ff / 32, Cc / 32, 1), 256>>>(w1, w1T, Ff, Cc, 1, 0, 0, 0, 0);
    transpose_f2h<<<dim3(Cc / 32, Ff / 32, 1), 256>>>(w2, w2T, Cc, Ff, 1, 0, 0, 0, 0);

    // v -> vT (per b,h: [T,D] -> [D,T])
    transpose_h2h<<<dim3(Dd / 32, Tt / 32, Bb * Hh), 256>>>(
        v, vt, Cc, Tt, Hh, TC, (long long)Dd, (long long)Hh * DT, DT);

    // fused causal attention
    flash_attn<<<dim3(Tt / 128, Bb * Hh), 256, FSMEM>>>(q, k, vt, o);

    // x1 = x + (O @ wo + bo)
    {
        dim3 g(Cc / 128, BT / 128, 1);
        hgemm<<<g, 256, SMEM_BYTES>>>(o, woT, x1, BT, Cc, Cc, Cc, Cc, Cc, 1.f,
                                      bo, x, 0, 0, 1, 0, 0, 0, 0, 0, 0);
    }

    // BN1 + LN2 fused
    bn_ln_kernel<<<Tt, 256>>>(x1, bn1_g, bn1_b, ln2_g, ln2_b, x2, h);

    // f1 = relu(h @ w1 + b1)
    {
        dim3 g(Ff / 128, BT / 128, 1);
        hgemm<<<g, 256, SMEM_BYTES>>>(h, w1T, (void*)f1, BT, Ff, Cc, Cc, Cc, Ff, 1.f,
                                      b1, nullptr, 1, 1, 1, 0, 0, 0, 0, 0, 0);
    }

    // f2 = x2 + (f1 @ w2 + b2)
    {
        dim3 g(Cc / 128, BT / 128, 1);
        hgemm<<<g, 256, SMEM_BYTES>>>(f1, w2T, f2, BT, Cc, Ff, Ff, Ff, Cc, 1.f,
                                      b2, x2, 0, 0, 1, 0, 0, 0, 0, 0, 0);
    }

    // bn2 -> out
    bn_kernel<<<Tt, 256>>>(f2, bn2_g, bn2_b, out);
}